// round 2
// baseline (speedup 1.0000x reference)
#include <cuda_runtime.h>
#include <cstdint>

#define NS    128      // states
#define NA    32       // alphabet
#define NB    64       // batch
#define NT    4096     // time steps

// ---------------- device scratch (no allocations allowed) ----------------
__device__ float g_At[NS * NS];          // A transposed: g_At[j*NS + i] = A[i][j]
__device__ float g_Bm[NA * NS];          // emission probs [a][s]
__device__ float g_I[NS];                // initial dist
__device__ unsigned char g_tok[NB * NT]; // decoded tokens

// ---------------- packed f32x2 helpers ----------------
__device__ __forceinline__ void ffma2(unsigned long long& d,
                                      unsigned long long a,
                                      unsigned long long b) {
    asm("fma.rn.f32x2 %0, %1, %2, %3;" : "=l"(d) : "l"(a), "l"(b), "l"(d));
}
__device__ __forceinline__ unsigned long long add2(unsigned long long a,
                                                   unsigned long long b) {
    unsigned long long d;
    asm("add.rn.f32x2 %0, %1, %2;" : "=l"(d) : "l"(a), "l"(b));
    return d;
}
__device__ __forceinline__ void unpack2(float& lo, float& hi, unsigned long long v) {
    asm("mov.b64 {%0, %1}, %2;" : "=f"(lo), "=f"(hi) : "l"(v));
}

// ---------------- preprocessing: softmaxes (parallelized) ----------------
// blocks 0..127: softmax of A row bid (axis 1), store transposed
// block 128:     softmax of B over alphabet per state (thread = state)
// block 129:     softmax of I
__global__ void prep_params(const float* __restrict__ A_logits,
                            const float* __restrict__ B_logits,
                            const float* __restrict__ I_logits) {
    const int bid = blockIdx.x;
    const int t = threadIdx.x;
    __shared__ float red[4];

    if (bid < NS) {
        float x = A_logits[bid * NS + t];
        float m = x;
#pragma unroll
        for (int o = 16; o; o >>= 1) m = fmaxf(m, __shfl_xor_sync(~0u, m, o));
        if ((t & 31) == 0) red[t >> 5] = m;
        __syncthreads();
        m = fmaxf(fmaxf(red[0], red[1]), fmaxf(red[2], red[3]));
        float e = expf(x - m);
        float s = e;
#pragma unroll
        for (int o = 16; o; o >>= 1) s += __shfl_xor_sync(~0u, s, o);
        __syncthreads();
        if ((t & 31) == 0) red[t >> 5] = s;
        __syncthreads();
        s = (red[0] + red[1]) + (red[2] + red[3]);
        g_At[t * NS + bid] = e / s;
    } else if (bid == NS) {
        float m = -1e30f;
        for (int a = 0; a < NA; a++) m = fmaxf(m, B_logits[a * NS + t]);
        float s = 0.f;
        for (int a = 0; a < NA; a++) s += expf(B_logits[a * NS + t] - m);
        float inv = 1.f / s;
        for (int a = 0; a < NA; a++)
            g_Bm[a * NS + t] = expf(B_logits[a * NS + t] - m) * inv;
    } else {
        float x = I_logits[t];
        float m = x;
#pragma unroll
        for (int o = 16; o; o >>= 1) m = fmaxf(m, __shfl_xor_sync(~0u, m, o));
        if ((t & 31) == 0) red[t >> 5] = m;
        __syncthreads();
        m = fmaxf(fmaxf(red[0], red[1]), fmaxf(red[2], red[3]));
        float e = expf(x - m);
        float s = e;
#pragma unroll
        for (int o = 16; o; o >>= 1) s += __shfl_xor_sync(~0u, s, o);
        __syncthreads();
        if ((t & 31) == 0) red[t >> 5] = s;
        __syncthreads();
        s = (red[0] + red[1]) + (red[2] + red[3]);
        g_I[t] = e / s;
    }
}

// ---------------- preprocessing: one-hot -> token ----------------
__global__ void prep_tokens(const float* __restrict__ inputs) {
    int n = blockIdx.x * blockDim.x + threadIdx.x;
    if (n >= NB * NT) return;
    const float4* p = (const float4*)(inputs + (size_t)n * NA);
    int tok = 0;
#pragma unroll
    for (int k = 0; k < 8; k++) {
        float4 v = p[k];
        if (v.x > 0.5f) tok = 4 * k;
        if (v.y > 0.5f) tok = 4 * k + 1;
        if (v.z > 0.5f) tok = 4 * k + 2;
        if (v.w > 0.5f) tok = 4 * k + 3;
    }
    g_tok[n] = (unsigned char)tok;
}

// ---------------- forward recurrence: 1 CTA per batch, 512 threads ----------------
// Thread tid: output state j = tid>>2, quarter h = tid&3 handles rows i in
// [32h, 32h+32). Partial dots combined with 2 intra-quad shfl_xor.
// alpha stored in a PADDED layout (chunk stride 36 floats = 144B) so the four
// h-chunks hit disjoint banks: bank(144h + 16k) = 4h + 4k (mod 32).
__global__ void __launch_bounds__(512, 1) hmm_forward(float* __restrict__ out) {
    const int b = blockIdx.x;
    const int tid = threadIdx.x;
    const int j = tid >> 2;
    const int h = tid & 3;
    const int w = tid >> 5;
    const int l = tid & 31;

    __shared__ float sB[NA * NS];                     // 16 KB emission table
    __shared__ __align__(16) unsigned char sTok[NT];  // 4 KB tokens
    __shared__ __align__(16) float sAl[2][4 * 36];    // padded ping-pong alpha
    __shared__ float sPart[16];

    // stage emission table (4096 floats = 1024 float4)
    {
        const float4* src = (const float4*)g_Bm;
        float4* dst = (float4*)sB;
        dst[tid] = src[tid];
        dst[tid + 512] = src[tid + 512];
    }
    // stage tokens (4096 B = 256 int4)
    if (tid < 256) {
        ((int4*)sTok)[tid] = ((const int4*)(g_tok + (size_t)b * NT))[tid];
    }

    // A column j, rows 32h..32h+31 -> 16 packed f32x2 in registers
    unsigned long long aR[16];
    {
        const ulonglong2* gp = (const ulonglong2*)(g_At + (size_t)j * NS + h * 32);
#pragma unroll
        for (int k = 0; k < 8; k++) {
            ulonglong2 q = gp[k];
            aR[2 * k] = q.x;
            aR[2 * k + 1] = q.y;
        }
    }
    const float Ij = g_I[j];
    // byte offset of alpha[j] inside the padded buffer
    const int wOff = (j >> 5) * 144 + (j & 31) * 4;
    __syncthreads();

    // t = 0: alpha = I * E_0 (unnormalized; renorm cadence handles scaling)
    if (h == 0) {
        int tok = sTok[0];
        *(float*)((char*)sAl[0] + wOff) = Ij * sB[tok * NS + j];
    }
    __syncthreads();

    const char* rp = (const char*)sAl[0] + 144 * h;  // read base (this thread's chunk)
    const char* rq = (const char*)sAl[1] + 144 * h;
    char* wp = (char*)sAl[1] + wOff;                 // write addr for alpha[j]
    char* wq = (char*)sAl[0] + wOff;

    double loglik = 0.0;

    for (int t = 1; t < NT; t++) {
        int tok = sTok[t];
        float e = sB[tok * NS + j];

        unsigned long long acc0 = 0ull, acc1 = 0ull;
#pragma unroll
        for (int k = 0; k < 8; k++) {
            ulonglong2 q = *(const ulonglong2*)(rp + 16 * k);
            ffma2(acc0, q.x, aR[2 * k]);
            ffma2(acc1, q.y, aR[2 * k + 1]);
        }
        acc0 = add2(acc0, acc1);
        float lo, hi;
        unpack2(lo, hi, acc0);
        float p = lo + hi;
        // combine the 4 quarter-dots within the quad
        p += __shfl_xor_sync(~0u, p, 1);
        p += __shfl_xor_sync(~0u, p, 2);
        float v = p * e;

        if ((t & 7) == 7) {  // renormalize every 8 steps (incl. final t=4095)
            float r = v;     // equal within quad; reduce across the 8 quads
            r += __shfl_xor_sync(~0u, r, 4);
            r += __shfl_xor_sync(~0u, r, 8);
            r += __shfl_xor_sync(~0u, r, 16);
            if (l == 0) sPart[w] = r;
            __syncthreads();
            float4 p0 = ((float4*)sPart)[0];
            float4 p1 = ((float4*)sPart)[1];
            float4 p2 = ((float4*)sPart)[2];
            float4 p3 = ((float4*)sPart)[3];
            float S = ((p0.x + p0.y) + (p0.z + p0.w)) +
                      ((p1.x + p1.y) + (p1.z + p1.w)) +
                      ((p2.x + p2.y) + (p2.z + p2.w)) +
                      ((p3.x + p3.y) + (p3.z + p3.w));
            v *= __fdividef(1.0f, S);
            if (tid == 0) loglik += (double)__logf(S);
        }

        if (h == 0) *(float*)wp = v;
        __syncthreads();

        // swap ping-pong pointers
        const char* tr = rp; rp = rq; rq = tr;
        char* tw = wp; wp = wq; wq = tw;
    }

    if (tid == 0) out[b] = (float)loglik;
}

// ---------------- launch ----------------
extern "C" void kernel_launch(void* const* d_in, const int* in_sizes, int n_in,
                              void* d_out, int out_size) {
    const float* inputs = nullptr;   // 64*4096*32 = 8388608
    const float* A_logits = nullptr; // 128*128    = 16384
    const float* B_logits = nullptr; // 32*128     = 4096
    const float* I_logits = nullptr; // 128
    for (int i = 0; i < n_in; i++) {
        switch (in_sizes[i]) {
            case NB * NT * NA: inputs = (const float*)d_in[i]; break;
            case NS * NS:      A_logits = (const float*)d_in[i]; break;
            case NA * NS:      B_logits = (const float*)d_in[i]; break;
            case NS:           I_logits = (const float*)d_in[i]; break;
        }
    }
    float* out = (float*)d_out;

    prep_params<<<NS + 2, 128>>>(A_logits, B_logits, I_logits);
    prep_tokens<<<(NB * NT + 255) / 256, 256>>>(inputs);
    hmm_forward<<<NB, 512>>>(out);
}

// round 3
// speedup vs baseline: 1.8598x; 1.8598x over previous
#include <cuda_runtime.h>
#include <cstdint>

#define NS 128
#define NA 32
#define NB 64
#define NT 4096
#define THREADS 256

typedef unsigned long long ull;

__device__ __forceinline__ void ffma2(ull& d, ull a, ull b) {
    asm("fma.rn.f32x2 %0, %1, %2, %3;" : "=l"(d) : "l"(a), "l"(b), "l"(d));
}
__device__ __forceinline__ ull add2(ull a, ull b) {
    ull d; asm("add.rn.f32x2 %0, %1, %2;" : "=l"(d) : "l"(a), "l"(b)); return d;
}
__device__ __forceinline__ void unpack2(float& lo, float& hi, ull v) {
    asm("mov.b64 {%0, %1}, %2;" : "=f"(lo), "=f"(hi) : "l"(v));
}
__device__ __forceinline__ ull pack2(float lo, float hi) {
    ull d; asm("mov.b64 %0, {%1, %2};" : "=l"(d) : "f"(lo), "f"(hi)); return d;
}

// One fused kernel: per-CTA parameter softmaxes + token decode + forward loop.
// Thread layout: tid = 2*j + h.  j in [0,128) = output state, h in {0,1} = half
// of the inner 128-dot (rows [64h, 64h+64)).  Combine halves: shfl_xor(1).
// Alpha buffer padded: chunk0 at float-offset 0, chunk1 at 72 (=288B) so the
// two 16B lines read by one LDS.128 hit disjoint banks (1 wavefront).
__global__ void __launch_bounds__(THREADS, 1)
hmm_all(const float* __restrict__ inputs,
        const float* __restrict__ Al,
        const float* __restrict__ Bl,
        const float* __restrict__ Il,
        float* __restrict__ out) {
    const int b    = blockIdx.x;
    const int tid  = threadIdx.x;
    const int j    = tid >> 1;
    const int h    = tid & 1;
    const int lane = tid & 31;
    const int warp = tid >> 5;

    __shared__ float sB[NA * NS];                      // 16 KB emissions
    __shared__ __align__(16) unsigned char sTok[NT];   // 4 KB tokens
    __shared__ __align__(16) float sAl[2][144];        // padded ping-pong alpha
    __shared__ float sPart[8];
    __shared__ float sMaxA[NS], sInvA[NS];
    __shared__ float sI[NS];

    // ---- prep: A row stats (softmax over axis 1) ----
    if (tid < NS) {
        const float* rp = Al + tid * NS;
        float m = -1e30f;
        for (int k = 0; k < NS; k += 4) {
            float4 v = *(const float4*)(rp + k);
            m = fmaxf(m, fmaxf(fmaxf(v.x, v.y), fmaxf(v.z, v.w)));
        }
        float s = 0.f;
        for (int k = 0; k < NS; k += 4) {
            float4 v = *(const float4*)(rp + k);
            s += __expf(v.x - m) + __expf(v.y - m) + __expf(v.z - m) + __expf(v.w - m);
        }
        sMaxA[tid] = m;
        sInvA[tid] = 1.f / s;
    }
    // ---- prep: I softmax ----
    if (tid < NS) {
        float m = -1e30f;
        for (int k = 0; k < NS; k++) m = fmaxf(m, Il[k]);
        float s = 0.f;
        for (int k = 0; k < NS; k++) s += __expf(Il[k] - m);
        sI[tid] = __expf(Il[tid] - m) / s;
    }
    // ---- prep: B softmax over alphabet, per state column ----
    if (tid < NS) {
        float m = -1e30f;
        for (int a = 0; a < NA; a++) m = fmaxf(m, Bl[a * NS + tid]);
        float s = 0.f;
        for (int a = 0; a < NA; a++) s += __expf(Bl[a * NS + tid] - m);
        float inv = 1.f / s;
        for (int a = 0; a < NA; a++)
            sB[a * NS + tid] = __expf(Bl[a * NS + tid] - m) * inv;
    }
    // ---- prep: one-hot -> token (dot with iota; FFMA-imm) ----
#pragma unroll
    for (int c = 0; c < NT / THREADS; c++) {
        int n = c * THREADS + tid;
        const float4* p = (const float4*)(inputs + ((size_t)b * NT + n) * NA);
        float tk = 0.f;
#pragma unroll
        for (int k = 0; k < 8; k++) {
            float4 v = p[k];
            tk += v.x * (float)(4 * k) + v.y * (float)(4 * k + 1) +
                  v.z * (float)(4 * k + 2) + v.w * (float)(4 * k + 3);
        }
        sTok[n] = (unsigned char)(int)(tk + 0.5f);
    }
    __syncthreads();

    // ---- A-column registers: rows [64h, 64h+64) of column j, packed f32x2 ----
    ull aR[32];
#pragma unroll
    for (int k = 0; k < 32; k++) {
        int i0 = (h << 6) + 2 * k;
        float a0 = __expf(Al[i0 * NS + j] - sMaxA[i0]) * sInvA[i0];
        float a1 = __expf(Al[(i0 + 1) * NS + j] - sMaxA[i0 + 1]) * sInvA[i0 + 1];
        aR[k] = pack2(a0, a1);
    }

    const int wOff = j + ((j >> 6) << 3);  // padded write offset for alpha[j]

    // ---- t = 0 init (unnormalized; renorm cadence handles scaling) ----
    {
        int tok = sTok[0];
        if (h == 0) sAl[0][wOff] = sI[j] * sB[tok * NS + j];
    }
    __syncthreads();

    double loglik = 0.0;

    auto step = [&](int t, const float* rd, float* wr) {
        int tok = sTok[t];
        float e = sB[tok * NS + j];
        const ulonglong2* al = (const ulonglong2*)((const char*)rd + h * 288);
        ull acc0 = 0ull, acc1 = 0ull, acc2 = 0ull, acc3 = 0ull;
#pragma unroll
        for (int k = 0; k < 16; k += 2) {
            ulonglong2 q0 = al[k];
            ffma2(acc0, q0.x, aR[2 * k]);
            ffma2(acc1, q0.y, aR[2 * k + 1]);
            ulonglong2 q1 = al[k + 1];
            ffma2(acc2, q1.x, aR[2 * k + 2]);
            ffma2(acc3, q1.y, aR[2 * k + 3]);
        }
        acc0 = add2(acc0, acc2);
        acc1 = add2(acc1, acc3);
        acc0 = add2(acc0, acc1);
        float lo, hi;
        unpack2(lo, hi, acc0);
        float p = lo + hi;
        p += __shfl_xor_sync(0xffffffffu, p, 1);  // combine the two halves
        float v = p * e;

        if ((t & 7) == 7) {  // renormalize every 8 steps (incl. final t=4095)
            float w = v;
            w += __shfl_xor_sync(0xffffffffu, w, 2);
            w += __shfl_xor_sync(0xffffffffu, w, 4);
            w += __shfl_xor_sync(0xffffffffu, w, 8);
            w += __shfl_xor_sync(0xffffffffu, w, 16);
            if (lane == 0) sPart[warp] = w;
            __syncthreads();
            float4 q0 = ((const float4*)sPart)[0];
            float4 q1 = ((const float4*)sPart)[1];
            float S = 0.5f * (((q0.x + q0.y) + (q0.z + q0.w)) +
                              ((q1.x + q1.y) + (q1.z + q1.w)));
            v *= __fdividef(1.0f, S);
            loglik += (double)__logf(S);
        }

        if (h == 0) wr[wOff] = v;
        __syncthreads();
    };

    for (int t = 1; t < NT - 1; t += 2) {
        step(t, sAl[0], sAl[1]);
        step(t + 1, sAl[1], sAl[0]);
    }
    step(NT - 1, sAl[0], sAl[1]);  // t=4095, (t&7)==7 -> renorm, loglik complete

    if (tid == 0) out[b] = (float)loglik;
}

// ---------------- launch ----------------
extern "C" void kernel_launch(void* const* d_in, const int* in_sizes, int n_in,
                              void* d_out, int out_size) {
    const float* inputs = nullptr;   // 64*4096*32 = 8388608
    const float* A_logits = nullptr; // 128*128    = 16384
    const float* B_logits = nullptr; // 32*128     = 4096
    const float* I_logits = nullptr; // 128
    for (int i = 0; i < n_in; i++) {
        switch (in_sizes[i]) {
            case NB * NT * NA: inputs = (const float*)d_in[i]; break;
            case NS * NS:      A_logits = (const float*)d_in[i]; break;
            case NA * NS:      B_logits = (const float*)d_in[i]; break;
            case NS:           I_logits = (const float*)d_in[i]; break;
        }
    }
    hmm_all<<<NB, THREADS>>>(inputs, A_logits, B_logits, I_logits, (float*)d_out);
}